// round 1
// baseline (speedup 1.0000x reference)
#include <cuda_runtime.h>
#include <cuda_bf16.h>

// SiLU: y = x * sigmoid(x), elementwise over 4*4096*4096 fp32.
// Pure streaming kernel: float4 vectorized, fast-math sigmoid.

__device__ __forceinline__ float silu1(float x) {
    // sigmoid via fast exp; rel err ~1e-7, well under 1e-3 gate
    return x * (1.0f / (1.0f + __expf(-x)));
}

__global__ void silu_kernel_v4(const float4* __restrict__ in,
                               float4* __restrict__ out,
                               int n4) {
    int i = blockIdx.x * blockDim.x + threadIdx.x;
    if (i < n4) {
        float4 v = in[i];
        float4 r;
        r.x = silu1(v.x);
        r.y = silu1(v.y);
        r.z = silu1(v.z);
        r.w = silu1(v.w);
        out[i] = r;
    }
}

// Scalar tail (n not divisible by 4) — not needed for this shape but safe.
__global__ void silu_kernel_tail(const float* __restrict__ in,
                                 float* __restrict__ out,
                                 int start, int n) {
    int i = start + blockIdx.x * blockDim.x + threadIdx.x;
    if (i < n) out[i] = silu1(in[i]);
}

extern "C" void kernel_launch(void* const* d_in, const int* in_sizes, int n_in,
                              void* d_out, int out_size) {
    const float* x = (const float*)d_in[0];
    float* y = (float*)d_out;
    int n = in_sizes[0];

    int n4 = n / 4;
    if (n4 > 0) {
        int threads = 256;
        int blocks = (n4 + threads - 1) / threads;
        silu_kernel_v4<<<blocks, threads>>>((const float4*)x, (float4*)y, n4);
    }
    int rem = n - n4 * 4;
    if (rem > 0) {
        silu_kernel_tail<<<1, 256>>>(x, y, n4 * 4, n);
    }
}

// round 2
// speedup vs baseline: 1.0691x; 1.0691x over previous
#include <cuda_runtime.h>
#include <cuda_bf16.h>

// SiLU y = x*sigmoid(x), streaming fp32. R2: 4x float4 per thread with
// front-batched loads (MLP=4) + streaming cache hints (.cs) since data
// has zero reuse.

__device__ __forceinline__ float silu1(float x) {
    return x * (1.0f / (1.0f + __expf(-x)));
}

__device__ __forceinline__ float4 silu4(float4 v) {
    float4 r;
    r.x = silu1(v.x);
    r.y = silu1(v.y);
    r.z = silu1(v.z);
    r.w = silu1(v.w);
    return r;
}

#define VPT 4  // float4s per thread

__global__ void __launch_bounds__(256)
silu_kernel_v4x4(const float4* __restrict__ in,
                 float4* __restrict__ out,
                 int n4) {
    int base = blockIdx.x * (blockDim.x * VPT) + threadIdx.x;

    if (base + (VPT - 1) * blockDim.x < n4) {
        // Fast path: all 4 loads issued back-to-back (MLP_p1 = 4)
        float4 v0 = __ldcs(&in[base + 0 * blockDim.x]);
        float4 v1 = __ldcs(&in[base + 1 * blockDim.x]);
        float4 v2 = __ldcs(&in[base + 2 * blockDim.x]);
        float4 v3 = __ldcs(&in[base + 3 * blockDim.x]);
        __stcs(&out[base + 0 * blockDim.x], silu4(v0));
        __stcs(&out[base + 1 * blockDim.x], silu4(v1));
        __stcs(&out[base + 2 * blockDim.x], silu4(v2));
        __stcs(&out[base + 3 * blockDim.x], silu4(v3));
    } else {
        #pragma unroll
        for (int k = 0; k < VPT; k++) {
            int i = base + k * blockDim.x;
            if (i < n4) __stcs(&out[i], silu4(__ldcs(&in[i])));
        }
    }
}

__global__ void silu_kernel_tail(const float* __restrict__ in,
                                 float* __restrict__ out,
                                 int start, int n) {
    int i = start + blockIdx.x * blockDim.x + threadIdx.x;
    if (i < n) out[i] = silu1(in[i]);
}

extern "C" void kernel_launch(void* const* d_in, const int* in_sizes, int n_in,
                              void* d_out, int out_size) {
    const float* x = (const float*)d_in[0];
    float* y = (float*)d_out;
    int n = in_sizes[0];

    int n4 = n / 4;
    if (n4 > 0) {
        int threads = 256;
        int per_block = threads * VPT;
        int blocks = (n4 + per_block - 1) / per_block;
        silu_kernel_v4x4<<<blocks, threads>>>((const float4*)x, (float4*)y, n4);
    }
    int rem = n - n4 * 4;
    if (rem > 0) {
        silu_kernel_tail<<<1, 256>>>(x, y, n4 * 4, n);
    }
}